// round 1
// baseline (speedup 1.0000x reference)
#include <cuda_runtime.h>

// AvgPool2d 64x64, stride 1, replicate edge-pad. x: (16,64,256,256) fp32.
// One CTA per (n,c) image. Phase 1: per-row prefix sums -> horizontal 64-window
// sums H[256][193] in smem. Phase 2: per-thread vertical sliding 64-window over
// one (pre-clamped) output column; coalesced row writes with edge replication.

#define IMG_ELEMS 65536        // 256*256
#define HSTR 193               // odd stride -> conflict-free column walks
#define PE_STR 272             // per-warp prefix scratch stride (max idx 264)
#define SMEM_FLOATS (256 * HSTR + 16 * PE_STR)
#define SMEM_BYTES (SMEM_FLOATS * 4)

__device__ __forceinline__ int pad_idx(int j) { return j + (j >> 5); }

__global__ __launch_bounds__(512, 1)
void avgpool64_kernel(const float* __restrict__ x, float* __restrict__ out) {
    extern __shared__ float smem[];
    float* Hs = smem;                    // [256][HSTR]
    float* PeAll = smem + 256 * HSTR;    // [16][PE_STR]

    const int tid  = threadIdx.x;
    const int wid  = tid >> 5;
    const int lane = tid & 31;

    const float* img    = x   + (size_t)blockIdx.x * IMG_ELEMS;
    float*       outImg = out + (size_t)blockIdx.x * IMG_ELEMS;
    float* pe = PeAll + wid * PE_STR;

    // ---------------- Phase 1: horizontal window sums ----------------
    // Warp `wid` handles rows [wid*16, wid*16+16).
    const int row0 = wid * 16;
    const float4* rp = (const float4*)(img + row0 * 256);  // 64 float4 per row

    float4 a = rp[lane * 2];
    float4 b = rp[lane * 2 + 1];

    #pragma unroll 1
    for (int r = 0; r < 16; ++r) {
        float4 na, nb;
        if (r < 15) {                       // prefetch next row
            na = rp[(r + 1) * 64 + lane * 2];
            nb = rp[(r + 1) * 64 + lane * 2 + 1];
        }

        // local inclusive prefix over this lane's 8 values
        float p0 = a.x;
        float p1 = p0 + a.y;
        float p2 = p1 + a.z;
        float p3 = p2 + a.w;
        float p4 = p3 + b.x;
        float p5 = p4 + b.y;
        float p6 = p5 + b.z;
        float p7 = p6 + b.w;
        float s = p7;

        // warp inclusive scan of lane totals
        float t = s;
        #pragma unroll
        for (int o = 1; o < 32; o <<= 1) {
            float u = __shfl_up_sync(0xffffffffu, t, o);
            if (lane >= o) t += u;
        }
        float excl = t - s;  // exclusive prefix of lane totals

        // exclusive row prefix Pe[j]: Pe[0]=0, Pe[j] = sum x[0..j-1]
        const int base = lane * 8;
        pe[pad_idx(base + 1)] = excl + p0;
        pe[pad_idx(base + 2)] = excl + p1;
        pe[pad_idx(base + 3)] = excl + p2;
        pe[pad_idx(base + 4)] = excl + p3;
        pe[pad_idx(base + 5)] = excl + p4;
        pe[pad_idx(base + 6)] = excl + p5;
        pe[pad_idx(base + 7)] = excl + p6;
        pe[pad_idx(base + 8)] = excl + p7;
        if (lane == 0) pe[pad_idx(0)] = 0.0f;
        __syncwarp();

        float* Hrow = Hs + (row0 + r) * HSTR;
        #pragma unroll
        for (int bs = 0; bs < 193; bs += 32) {
            int oj = bs + lane;
            if (oj < 193)
                Hrow[oj] = pe[pad_idx(oj + 64)] - pe[pad_idx(oj)];
        }
        __syncwarp();   // protect pe reuse next iteration

        a = na; b = nb;
    }

    __syncthreads();

    // ---------------- Phase 2: vertical sliding window ----------------
    // Thread owns output column j (0..255) with clamped source column cj.
    // Two groups split the y range to halve the sequential slide chain.
    const int g = tid >> 8;          // 0: y in [0,128)   1: y in [128,256)
    const int j = tid & 255;
    int cj = j - 31;
    cj = cj < 0 ? 0 : (cj > 192 ? 192 : cj);
    const float* Hc = Hs + cj;
    const float inv = 1.0f / 4096.0f;

    if (g == 0) {
        // init: box sum rows [0,64)
        float s0 = 0.f, s1 = 0.f, s2 = 0.f, s3 = 0.f;
        #pragma unroll
        for (int i = 0; i < 64; i += 4) {
            s0 += Hc[(i + 0) * HSTR];
            s1 += Hc[(i + 1) * HSTR];
            s2 += Hc[(i + 2) * HSTR];
            s3 += Hc[(i + 3) * HSTR];
        }
        float s = (s0 + s1) + (s2 + s3);

        float v = s * inv;               // box[0] -> rows y=0..31
        #pragma unroll
        for (int y = 0; y < 32; ++y) outImg[y * 256 + j] = v;

        #pragma unroll 4
        for (int oi = 1; oi <= 96; ++oi) {
            s += Hc[(oi + 63) * HSTR] - Hc[(oi - 1) * HSTR];
            outImg[(oi + 31) * 256 + j] = s * inv;   // y = 32..127
        }
    } else {
        // init: box sum rows [97,161) -> box[97] (y=128)
        float s0 = 0.f, s1 = 0.f, s2 = 0.f, s3 = 0.f;
        #pragma unroll
        for (int i = 97; i < 161; i += 4) {
            s0 += Hc[(i + 0) * HSTR];
            s1 += Hc[(i + 1) * HSTR];
            s2 += Hc[(i + 2) * HSTR];
            s3 += Hc[(i + 3) * HSTR];
        }
        float s = (s0 + s1) + (s2 + s3);
        outImg[128 * 256 + j] = s * inv;             // y = 128

        #pragma unroll 4
        for (int oi = 98; oi <= 192; ++oi) {
            s += Hc[(oi + 63) * HSTR] - Hc[(oi - 1) * HSTR];
            outImg[(oi + 31) * 256 + j] = s * inv;   // y = 129..223
        }

        float v = s * inv;               // box[192] -> rows y=224..255
        #pragma unroll
        for (int y = 224; y < 256; ++y) outImg[y * 256 + j] = v;
    }
}

extern "C" void kernel_launch(void* const* d_in, const int* in_sizes, int n_in,
                              void* d_out, int out_size) {
    const float* x = (const float*)d_in[0];
    float* out = (float*)d_out;
    const int n_images = in_sizes[0] / IMG_ELEMS;   // 16*64 = 1024

    cudaFuncSetAttribute(avgpool64_kernel,
                         cudaFuncAttributeMaxDynamicSharedMemorySize, SMEM_BYTES);
    avgpool64_kernel<<<n_images, 512, SMEM_BYTES>>>(x, out);
}

// round 2
// speedup vs baseline: 1.3674x; 1.3674x over previous
#include <cuda_runtime.h>

// AvgPool2d 64x64, stride 1, replicate edge-pad. x: (16,64,256,256) fp32.
// One CTA per (n,c) image, 16-batch pipeline:
//   per batch: 16 warps compute 16 horizontal-window rows H[r][0..192] into an
//   80-row smem ring; 256 threads slide per-column vertical 64-window sums and
//   write 16 coalesced output rows. Prefetch for batch b+1 issued before the
//   warp scan so DRAM reads overlap scan/vertical/stores. 79 KB smem -> 2 CTAs/SM.

#define IMG_ELEMS 65536        // 256*256
#define HSTR 193               // odd stride -> conflict-free column walks
#define RING 80                // 64-row window + 16-row batch
#define PE_STR 272             // per-warp prefix scratch stride (max idx 264)
#define SMEM_FLOATS (RING * HSTR + 16 * PE_STR)
#define SMEM_BYTES (SMEM_FLOATS * 4)

__device__ __forceinline__ int pad_idx(int j) { return j + (j >> 5); }

__global__ __launch_bounds__(512, 2)
void avgpool64_pipe(const float* __restrict__ x, float* __restrict__ out) {
    extern __shared__ float smem[];
    float* Hs = smem;                                         // [RING][HSTR]
    float* pe = smem + RING * HSTR + (threadIdx.x >> 5) * PE_STR;

    const int tid  = threadIdx.x;
    const int wid  = tid >> 5;
    const int lane = tid & 31;

    const float* img    = x   + (size_t)blockIdx.x * IMG_ELEMS;
    float*       outImg = out + (size_t)blockIdx.x * IMG_ELEMS;

    // vertical state (threads 0..255 own output column tid)
    int cj = tid - 31;
    cj = cj < 0 ? 0 : (cj > 192 ? 192 : cj);
    float vs = 0.0f;
    const float inv = 1.0f / 4096.0f;

    const float4* rp = (const float4*)img;     // 64 float4 per image row
    float4 a = rp[wid * 64 + lane * 2];
    float4 b = rp[wid * 64 + lane * 2 + 1];

    int base = 0;                               // (16*bt) % RING
    #pragma unroll 1
    for (int bt = 0; bt < 16; ++bt) {
        const int r = bt * 16 + wid;            // this warp's input row

        // local inclusive prefix over this lane's 8 values
        float p0 = a.x;
        float p1 = p0 + a.y;
        float p2 = p1 + a.z;
        float p3 = p2 + a.w;
        float p4 = p3 + b.x;
        float p5 = p4 + b.y;
        float p6 = p5 + b.z;
        float p7 = p6 + b.w;

        // prefetch next batch's row ASAP (a,b dead) -> loads in flight through
        // the scan, smem writes, and the vertical section
        if (bt < 15) {
            a = rp[(r + 16) * 64 + lane * 2];
            b = rp[(r + 16) * 64 + lane * 2 + 1];
        }

        // warp inclusive scan of lane totals
        float t = p7;
        #pragma unroll
        for (int o = 1; o < 32; o <<= 1) {
            float u = __shfl_up_sync(0xffffffffu, t, o);
            if (lane >= o) t += u;
        }
        const float e = t - p7;                 // exclusive prefix of lane totals

        // exclusive row prefix Pe[j] = sum x[0..j-1], bank-padded
        const int bidx = lane * 8;
        pe[pad_idx(bidx + 1)] = e + p0;
        pe[pad_idx(bidx + 2)] = e + p1;
        pe[pad_idx(bidx + 3)] = e + p2;
        pe[pad_idx(bidx + 4)] = e + p3;
        pe[pad_idx(bidx + 5)] = e + p4;
        pe[pad_idx(bidx + 6)] = e + p5;
        pe[pad_idx(bidx + 7)] = e + p6;
        pe[pad_idx(bidx + 8)] = e + p7;
        if (lane == 0) pe[pad_idx(0)] = 0.0f;
        __syncwarp();

        // H[r][oj] = Pe[oj+64] - Pe[oj], oj = 0..192, into ring slot base+wid
        float* Hrow = Hs + (base + wid) * HSTR;
        #pragma unroll
        for (int bs = 0; bs < 193; bs += 32) {
            int oj = bs + lane;
            if (oj < 193)
                Hrow[oj] = pe[pad_idx(oj + 64)] - pe[pad_idx(oj)];
        }

        __syncthreads();   // H rows of this batch visible to all

        // ------- vertical sliding window: 16 steps, threads 0..255 -------
        if (tid < 256) {
            const float* Hn = Hs + base * HSTR + cj;     // new rows, +k*HSTR
            if (bt < 4) {
                // warmup: accumulate rows 0..63, no output yet
                #pragma unroll
                for (int k = 0; k < 16; ++k)
                    vs += Hn[k * HSTR];
                if (bt == 3) {                  // vs = box[0]; y = 0..31
                    float v = vs * inv;
                    #pragma unroll
                    for (int y = 0; y < 32; ++y)
                        outImg[y * 256 + tid] = v;
                }
            } else {
                // steady: slide + emit y = 16*bt+k-32 for k=0..15
                int sob = base + 16;                      // slot of row rr-64
                if (sob >= RING) sob -= RING;             // never splits a batch
                const float* Ho = Hs + sob * HSTR + cj;
                float* op = outImg + (bt * 16 - 32) * 256 + tid;
                #pragma unroll
                for (int k = 0; k < 16; ++k) {
                    vs += Hn[k * HSTR] - Ho[k * HSTR];
                    op[k * 256] = vs * inv;
                }
                if (bt == 15) {                 // vs = box[192]; y = 224..255
                    float v = vs * inv;
                    #pragma unroll
                    for (int y = 224; y < 256; ++y)
                        outImg[y * 256 + tid] = v;
                }
            }
        }

        __syncthreads();   // ring slots consumed before next batch overwrites
        base += 16;
        if (base >= RING) base -= RING;
    }
}

extern "C" void kernel_launch(void* const* d_in, const int* in_sizes, int n_in,
                              void* d_out, int out_size) {
    const float* x = (const float*)d_in[0];
    float* out = (float*)d_out;
    const int n_images = in_sizes[0] / IMG_ELEMS;   // 16*64 = 1024

    cudaFuncSetAttribute(avgpool64_pipe,
                         cudaFuncAttributeMaxDynamicSharedMemorySize, SMEM_BYTES);
    avgpool64_pipe<<<n_images, 512, SMEM_BYTES>>>(x, out);
}

// round 3
// speedup vs baseline: 1.4551x; 1.0641x over previous
#include <cuda_runtime.h>

// AvgPool2d 64x64, stride 1, replicate edge-pad. x: (16,64,256,256) fp32.
// One CTA per (n,c) image, 16-batch pipeline. Phase 1 computes horizontal
// 64-window sums ENTIRELY in registers (warp scan + cross-lane shuffle
// differences), storing H rows straight into a 96-row smem ring with two
// STS.128 per lane. One __syncthreads per batch (ring slack covers the
// store(b+1) / vertical(b) overlap). 256 threads slide per-column vertical
// 64-window sums and write coalesced output rows.

#define IMG_ELEMS 65536        // 256*256
#define HSTR 196               // 196 ≡ 0 mod 4 -> float4-aligned H rows
#define RING 96                // 64-row window + 16-row batch + 16 slack
#define SMEM_BYTES (RING * HSTR * 4)   // 75264 B -> 2 CTAs/SM

__global__ __launch_bounds__(512, 2)
void avgpool64_v3(const float* __restrict__ x, float* __restrict__ out) {
    extern __shared__ float Hs[];                 // [RING][HSTR]

    const int tid  = threadIdx.x;
    const int wid  = tid >> 5;
    const int lane = tid & 31;

    const float* img    = x   + (size_t)blockIdx.x * IMG_ELEMS;
    float*       outImg = out + (size_t)blockIdx.x * IMG_ELEMS;

    // vertical state (threads 0..255 own output column tid)
    int cj = tid - 31;
    cj = cj < 0 ? 0 : (cj > 192 ? 192 : cj);
    float vs = 0.0f;
    const float inv = 1.0f / 4096.0f;

    const float4* rp = (const float4*)img;        // 64 float4 per image row
    float4 a = rp[wid * 64 + lane * 2];
    float4 b = rp[wid * 64 + lane * 2 + 1];

    int base = 0;                                 // (16*bt) % RING
    #pragma unroll 1
    for (int bt = 0; bt < 16; ++bt) {
        const int r = bt * 16 + wid;              // this warp's input row

        // local inclusive prefix over this lane's 8 values
        float p0 = a.x;
        float p1 = p0 + a.y;
        float p2 = p1 + a.z;
        float p3 = p2 + a.w;
        float p4 = p3 + b.x;
        float p5 = p4 + b.y;
        float p6 = p5 + b.z;
        float p7 = p6 + b.w;

        // prefetch next batch's row ASAP (a,b dead) -> DRAM reads in flight
        // through scan + shuffles + stores + vertical
        if (bt < 15) {
            a = rp[(r + 16) * 64 + lane * 2];
            b = rp[(r + 16) * 64 + lane * 2 + 1];
        }

        // warp inclusive scan of lane totals
        float t = p7;
        #pragma unroll
        for (int o = 1; o < 32; o <<= 1) {
            float u = __shfl_up_sync(0xffffffffu, t, o);
            if (lane >= o) t += u;
        }
        const float e = t - p7;                   // global prefix at 8*lane-1

        // global inclusive prefixes q_k = P[8*lane+k]
        float q0 = e + p0, q1 = e + p1, q2 = e + p2, q3 = e + p3;
        float q4 = e + p4, q5 = e + p5, q6 = e + p6, q7 = e + p7;

        // H[j] = P[j+63] - P[j-1] via cross-lane differences:
        //   H[8l]   = q7(lane l+7) - e
        //   H[8l+k] = q_{k-1}(lane l+8) - q_{k-1},  k=1..7
        // lane 24's h0 = t31 - t23 = H[192].
        float s7 = __shfl_down_sync(0xffffffffu, q7, 7);
        float s0 = __shfl_down_sync(0xffffffffu, q0, 8);
        float s1 = __shfl_down_sync(0xffffffffu, q1, 8);
        float s2 = __shfl_down_sync(0xffffffffu, q2, 8);
        float s3 = __shfl_down_sync(0xffffffffu, q3, 8);
        float s4 = __shfl_down_sync(0xffffffffu, q4, 8);
        float s5 = __shfl_down_sync(0xffffffffu, q5, 8);
        float s6 = __shfl_down_sync(0xffffffffu, q6, 8);

        float h0 = s7 - e;
        float h1 = s0 - q0;
        float h2 = s1 - q1;
        float h3 = s2 - q2;
        float h4 = s3 - q3;
        float h5 = s4 - q4;
        float h6 = s5 - q5;
        float h7 = s6 - q6;

        float* Hrow = Hs + (base + wid) * HSTR;
        if (lane < 24) {
            float4 v0 = make_float4(h0, h1, h2, h3);
            float4 v1 = make_float4(h4, h5, h6, h7);
            float4* hp = (float4*)(Hrow + 8 * lane);
            hp[0] = v0;
            hp[1] = v1;
        } else if (lane == 24) {
            Hrow[192] = h0;
        }

        __syncthreads();   // H rows of batch bt visible; fences vertical(bt-1)

        // ------- vertical sliding window: 16 steps, threads 0..255 -------
        if (tid < 256) {
            const float* Hn = Hs + base * HSTR + cj;        // new rows
            if (bt < 4) {
                #pragma unroll
                for (int k = 0; k < 16; ++k)
                    vs += Hn[k * HSTR];
                if (bt == 3) {                    // vs = box[0]; y = 0..31
                    float v = vs * inv;
                    #pragma unroll
                    for (int y = 0; y < 32; ++y)
                        outImg[y * 256 + tid] = v;
                }
            } else {
                int sob = base + 32;                         // row r-64 slots
                if (sob >= RING) sob -= RING;                // never splits batch
                const float* Ho = Hs + sob * HSTR + cj;
                float* op = outImg + (bt * 16 - 32) * 256 + tid;
                #pragma unroll
                for (int k = 0; k < 16; ++k) {
                    vs += Hn[k * HSTR] - Ho[k * HSTR];
                    op[k * 256] = vs * inv;
                }
                if (bt == 15) {                   // vs = box[192]; y = 224..255
                    float v = vs * inv;
                    #pragma unroll
                    for (int y = 224; y < 256; ++y)
                        outImg[y * 256 + tid] = v;
                }
            }
        }

        base += 16;
        if (base >= RING) base -= RING;
    }
}

extern "C" void kernel_launch(void* const* d_in, const int* in_sizes, int n_in,
                              void* d_out, int out_size) {
    const float* x = (const float*)d_in[0];
    float* out = (float*)d_out;
    const int n_images = in_sizes[0] / IMG_ELEMS;   // 16*64 = 1024

    cudaFuncSetAttribute(avgpool64_v3,
                         cudaFuncAttributeMaxDynamicSharedMemorySize, SMEM_BYTES);
    avgpool64_v3<<<n_images, 512, SMEM_BYTES>>>(x, out);
}